// round 17
// baseline (speedup 1.0000x reference)
#include <cuda_runtime.h>
#include <cuda_bf16.h>
#include <cstdint>

#define N_ATOMS   50000
#define NUM_ELEM  10
#define LMAX      3
#define SH_DIM    16
#define CIN       128
#define COUT      128
#define TILE_M    128
#define NSEG      (NUM_ELEM * (LMAX + 1))
#define GRID_PERS 296                     // 2 CTAs per SM, persistent
#define THREADS   128                     // 4 warps, 64x64 warp tiles
#define PAN_W     20                      // fp32 words per panel row (16 + 4 pad)
#define PAN_BYTES (TILE_M * PAN_W * 4)    // 10240
#define NSTAGE    4
#define HBLK      196                     // hist blocks (256 thr each)
#define WBLK      640                     // wpack blocks

// SMEM layout (bytes)
#define SM_APAN   0
#define SM_BS     (NSTAGE * PAN_BYTES)            // 40960
#define SM_PREFIX (SM_BS + 65536)                 // 106496, 41 ints
#define SM_CNT    (SM_PREFIX + 176)               // 106672
#define SM_OFF    (SM_CNT + 40)                   // 106712
#define SMEM_BYTES (SM_OFF + 40)                  // 106752

__device__ int   g_counts[NUM_ELEM];
__device__ int   g_offsets[NUM_ELEM];
__device__ int   g_species[N_ATOMS];
__device__ int   g_rank[N_ATOMS];
__device__ int   g_order[N_ATOMS];
__device__ int   g_pcnt[HBLK * NUM_ELEM];
__device__ int   g_pbase[HBLK * NUM_ELEM];
__device__ int   g_tile_prefix[NSEG + 1];
// W packed in tf32 mma B-fragment layout, PRE-SCALED by 1/sqrt(128):
// [seg][ks16(8)][nt(16)][lane(32)] -> uint4 {s0.b0, s0.b1, s1.b0, s1.b1}
__device__ uint4 g_wpack[NSEG * 4096];

// ---------------- helpers ----------------

__device__ __forceinline__ unsigned f2tf32(float v) {
    unsigned u;
    asm("cvt.rna.tf32.f32 %0, %1;" : "=r"(u) : "f"(v));
    return u;
}

__device__ __forceinline__ void mma_tf32(float* c, unsigned a0, unsigned a1,
                                         unsigned a2, unsigned a3,
                                         unsigned b0, unsigned b1) {
    asm volatile(
        "mma.sync.aligned.m16n8k8.row.col.f32.tf32.tf32.f32 "
        "{%0,%1,%2,%3}, {%4,%5,%6,%7}, {%8,%9}, {%0,%1,%2,%3};\n"
        : "+f"(c[0]), "+f"(c[1]), "+f"(c[2]), "+f"(c[3])
        : "r"(a0), "r"(a1), "r"(a2), "r"(a3), "r"(b0), "r"(b1));
}

__device__ __forceinline__ void cp16(uint32_t dst, const void* src, int srcsize) {
    asm volatile("cp.async.cg.shared.global [%0], [%1], 16, %2;"
                 :: "r"(dst), "l"(src), "r"(srcsize));
}

// magic multipliers for unsigned division by R = 2l+1 via (r*M)>>22
__device__ __forceinline__ unsigned magicM(int l) {
    return (l == 0) ? 4194304u : (l == 1) ? 1398102u
         : (l == 2) ? 838861u  : 599187u;
}

// row base offset in x/out for logical segment-row r (or -1 if OOB)
__device__ __forceinline__ int rowfor(int r, int Mseg, int l, int offe,
                                      unsigned M, int R) {
    if (r >= Mseg) return -1;
    unsigned q = (unsigned)(((unsigned long long)(unsigned)r * M) >> 22);
    int rem = r - (int)(q * (unsigned)R);
    int atom = g_order[offe + (int)q];
    return (atom * SH_DIM + l * l + rem) * CIN;
}

// ---------------- prep kernels (3 launches total) ----------------

// Blocks 0..HBLK-1: per-block histogram (partial counts + local rank, no
// global atomics). Blocks HBLK..HBLK+WBLK-1: W fragment pack (independent).
__global__ void k_prep(const float* __restrict__ y, const float* __restrict__ w) {
    int tid = threadIdx.x;
    if (blockIdx.x < HBLK) {
        __shared__ int cnt[NUM_ELEM];
        if (tid < NUM_ELEM) cnt[tid] = 0;
        __syncthreads();
        int n = blockIdx.x * 256 + tid;
        if (n < N_ATOMS) {
            const float* yr = y + (long)n * NUM_ELEM;
            float best = yr[0]; int s = 0;
#pragma unroll
            for (int e = 1; e < NUM_ELEM; e++) {
                float v = yr[e];
                if (v > best) { best = v; s = e; }
            }
            g_species[n] = s;
            g_rank[n] = atomicAdd(&cnt[s], 1);
        }
        __syncthreads();
        if (tid < NUM_ELEM) g_pcnt[blockIdx.x * NUM_ELEM + tid] = cnt[tid];
    } else {
        int idx = (blockIdx.x - HBLK) * 256 + tid;
        if (idx >= NSEG * 4096) return;
        int seg = idx >> 12;
        int rem = idx & 4095;
        int ks = rem >> 9;
        int nt = (rem >> 5) & 15;
        int t  = rem & 31;
        int tig = t & 3;
        int n  = nt * 8 + (t >> 2);
        const float scale = 0.08838834764831845f;
        const float* W = w + (long)seg * CIN * COUT;
        int k0 = ks * 16;
        unsigned b00 = f2tf32(scale * W[(k0 + tig         ) * COUT + n]);
        unsigned b01 = f2tf32(scale * W[(k0 + tig + 4     ) * COUT + n]);
        unsigned b10 = f2tf32(scale * W[(k0 + 8 + tig     ) * COUT + n]);
        unsigned b11 = f2tf32(scale * W[(k0 + 8 + tig + 4 ) * COUT + n]);
        g_wpack[idx] = make_uint4(b00, b01, b10, b11);
    }
}

// One block, 10 warps: warp e scans species e's per-block partial counts into
// exclusive bases + total; thread 0 then builds offsets + tile prefix.
__global__ void k_scan() {
    int tid  = threadIdx.x;
    int w    = tid >> 5;
    int lane = tid & 31;
    if (w < NUM_ELEM) {
        int run = 0;
        for (int j = 0; j < HBLK; j += 32) {
            int b = j + lane;
            int v = (b < HBLK) ? g_pcnt[b * NUM_ELEM + w] : 0;
            int incl = v;
#pragma unroll
            for (int d = 1; d < 32; d <<= 1) {
                int t = __shfl_up_sync(0xffffffffu, incl, d);
                if (lane >= d) incl += t;
            }
            if (b < HBLK) g_pbase[b * NUM_ELEM + w] = run + incl - v;
            run += __shfl_sync(0xffffffffu, incl, 31);
        }
        if (lane == 0) g_counts[w] = run;
    }
    __syncthreads();
    if (tid == 0) {
        int off = 0;
        for (int e = 0; e < NUM_ELEM; e++) { g_offsets[e] = off; off += g_counts[e]; }
        int tp = 0, seg = 0;
        g_tile_prefix[0] = 0;
        for (int e = 0; e < NUM_ELEM; e++)
            for (int l = 0; l <= LMAX; l++) {
                int rows = g_counts[e] * (2 * l + 1);
                tp += (rows + TILE_M - 1) / TILE_M;
                g_tile_prefix[++seg] = tp;
            }
    }
}

// Pure arithmetic scatter: pos = species offset + block base + local rank.
__global__ void k_scatter() {
    int n = blockIdx.x * 256 + threadIdx.x;
    if (n >= N_ATOMS) return;
    int s = g_species[n];
    int pos = g_offsets[s] + g_pbase[(n >> 8) * NUM_ELEM + s] + g_rank[n];
    g_order[pos] = n;
}

// ---------------- persistent tf32 tensor-core GEMM ----------------
// R15/16 structure; mainloop MMA schedule restructured so the two k8-steps of
// each accumulator are 16 MMAs apart (was back-to-back RAW at distance 1).
// N-tiles processed in two halves of 4 to keep only 4 B uint4 live.

__global__ __launch_bounds__(THREADS, 2)
void k_gemm(const float* __restrict__ x, float* __restrict__ out) {
    extern __shared__ char smraw[];
    float* Apan = (float*)(smraw + SM_APAN);     // [4][128][20]
    uint4* Bs   = (uint4*)(smraw + SM_BS);       // [8][16][32]
    int*   spre = (int*)(smraw + SM_PREFIX);     // [41]
    int*   scnt = (int*)(smraw + SM_CNT);        // [10]
    int*   soff = (int*)(smraw + SM_OFF);        // [10]

    int tid = threadIdx.x;
    if (tid <= NSEG) spre[tid] = g_tile_prefix[tid];
    if (tid < NUM_ELEM) { scnt[tid] = g_counts[tid]; soff[tid] = g_offsets[tid]; }
    __syncthreads();

    int ntiles = spre[NSEG];
    int q_  = ntiles / (int)gridDim.x;
    int r_  = ntiles % (int)gridDim.x;
    int bid = blockIdx.x;
    int t0   = bid * q_ + min(bid, r_);
    int tend = t0 + q_ + (bid < r_ ? 1 : 0);
    if (t0 >= tend) return;

    int seg = 0;
    while (spre[seg + 1] <= t0) seg++;

    int w    = tid >> 5;
    int lane = tid & 31;
    int g    = lane >> 2;
    int tig  = lane & 3;
    int mbase = (w & 1) * 64;       // 4 m-tiles per warp (64 rows)
    int ntb   = (w >> 1) * 8;       // 8 n-tiles (64 cols)
    int odd   = tig & 1;

    // per-thread cp.async: rows grow+32j (j<4), col-quad q (16B each)
    int grow = tid >> 2, q = tid & 3;
    uint32_t sb = (uint32_t)__cvta_generic_to_shared(Apan);
    uint32_t dj[4];
#pragma unroll
    for (int j = 0; j < 4; j++)
        dj[j] = sb + ((grow + 32 * j) * PAN_W + q * 4) * 4;

    // --- initial segment: fill B (64KB / 128 threads = 32 uint4 each) ---
    int cur_seg = seg;
    {
        const uint4* wp = g_wpack + seg * 4096;
#pragma unroll
        for (int i = 0; i < 32; i++) Bs[tid + i * 128] = wp[tid + i * 128];
    }
    __syncthreads();

    // --- tile t0: per-thread cp rows + prologue p0..p2 ---
    const float* cs[4]; int cz[4];
    {
        int l = seg & 3, e = seg >> 2;
        int R = 2 * l + 1;
        unsigned M = magicM(l);
        int Mseg = scnt[e] * R, offe = soff[e];
        int rbase = (t0 - spre[seg]) * TILE_M;
#pragma unroll
        for (int j = 0; j < 4; j++) {
            int rb = rowfor(rbase + grow + 32 * j, Mseg, l, offe, M, R);
            cs[j] = x + (rb < 0 ? 0 : rb) + q * 4;
            cz[j] = rb < 0 ? 0 : 16;
        }
    }
#pragma unroll
    for (int p = 0; p < NSTAGE - 1; p++) {
        uint32_t off = p * PAN_BYTES;
#pragma unroll
        for (int j = 0; j < 4; j++) cp16(dj[j] + off, cs[j] + p * 16, cz[j]);
        asm volatile("cp.async.commit_group;" ::: "memory");
    }

    float acc[4][8][4];
#pragma unroll
    for (int m = 0; m < 4; m++)
#pragma unroll
        for (int nt = 0; nt < 8; nt++)
#pragma unroll
            for (int i = 0; i < 4; i++) acc[m][nt][i] = 0.f;

    for (int t = t0; t < tend; t++) {
        int havenext = (t + 1 < tend);

        // ---- per-thread tile-start work ----
        int l = seg & 3, e = seg >> 2;
        int R = 2 * l + 1;
        unsigned M = magicM(l);
        int Mseg = scnt[e] * R, offe = soff[e];
        int rbase = (t - spre[seg]) * TILE_M;
        int rlo[4], rhi[4];
#pragma unroll
        for (int m = 0; m < 4; m++) {
            rlo[m] = rowfor(rbase + mbase + m * 16 + g,     Mseg, l, offe, M, R);
            rhi[m] = rowfor(rbase + mbase + m * 16 + g + 8, Mseg, l, offe, M, R);
        }
        // next tile: segment + cp rows (needed from ks5)
        int nseg = seg;
        const float* ns[4]; int nz[4];
#pragma unroll
        for (int j = 0; j < 4; j++) { ns[j] = cs[j]; nz[j] = cz[j]; }
        if (havenext) {
            while (spre[nseg + 1] <= t + 1) nseg++;
            int nl = nseg & 3, ne = nseg >> 2;
            int nR = 2 * nl + 1;
            unsigned nM = magicM(nl);
            int nMseg = scnt[ne] * nR, noffe = soff[ne];
            int nrbase = (t + 1 - spre[nseg]) * TILE_M;
#pragma unroll
            for (int j = 0; j < 4; j++) {
                int rb = rowfor(nrbase + grow + 32 * j, nMseg, nl, noffe, nM, nR);
                ns[j] = x + (rb < 0 ? 0 : rb) + q * 4;
                nz[j] = rb < 0 ? 0 : 16;
            }
        }

        // -------- mainloop: 8 k-steps, uniform steady-state pipeline --------
#pragma unroll
        for (int ks = 0; ks < 8; ks++) {
            if (havenext || ks < 6)
                asm volatile("cp.async.wait_group 2;" ::: "memory");
            else if (ks == 6)
                asm volatile("cp.async.wait_group 1;" ::: "memory");
            else
                asm volatile("cp.async.wait_group 0;" ::: "memory");
            __syncthreads();
            if (ks < 5) {          // this tile's panel ks+3
                uint32_t off = ((ks + 3) & (NSTAGE - 1)) * PAN_BYTES;
#pragma unroll
                for (int j = 0; j < 4; j++)
                    cp16(dj[j] + off, cs[j] + (ks + 3) * 16, cz[j]);
                asm volatile("cp.async.commit_group;" ::: "memory");
            } else if (havenext) { // next tile's panel ks-5
                int p = ks - 5;
                uint32_t off = (p & (NSTAGE - 1)) * PAN_BYTES;
#pragma unroll
                for (int j = 0; j < 4; j++)
                    cp16(dj[j] + off, ns[j] + p * 16, nz[j]);
                asm volatile("cp.async.commit_group;" ::: "memory");
            }
            const unsigned* A = (const unsigned*)Apan
                              + (ks & (NSTAGE - 1)) * (PAN_BYTES / 4);
            unsigned a[4][8];
#pragma unroll
            for (int m = 0; m < 4; m++) {
                const unsigned* Ar0 = A + (mbase + m * 16 + g) * PAN_W;
                const unsigned* Ar1 = Ar0 + 8 * PAN_W;
                a[m][0] = Ar0[tig];       a[m][1] = Ar1[tig];
                a[m][2] = Ar0[tig + 4];   a[m][3] = Ar1[tig + 4];
                a[m][4] = Ar0[tig + 8];   a[m][5] = Ar1[tig + 8];
                a[m][6] = Ar0[tig + 12];  a[m][7] = Ar1[tig + 12];
            }
            // n-tiles in two halves of 4; within a half, all 16 s0 MMAs
            // (distinct acc) issue before any s1 MMA reuses an acc ->
            // RAW distance 16 (was 1).
#pragma unroll
            for (int h = 0; h < 2; h++) {
                uint4 Bv[4];
#pragma unroll
                for (int i = 0; i < 4; i++)
                    Bv[i] = Bs[ks * 512 + (ntb + h * 4 + i) * 32 + lane];
#pragma unroll
                for (int i = 0; i < 4; i++) {
                    int ntl = h * 4 + i;
#pragma unroll
                    for (int m = 0; m < 4; m++)
                        mma_tf32(acc[m][ntl], a[m][0], a[m][1], a[m][2], a[m][3],
                                 Bv[i].x, Bv[i].y);
                }
#pragma unroll
                for (int i = 0; i < 4; i++) {
                    int ntl = h * 4 + i;
#pragma unroll
                    for (int m = 0; m < 4; m++)
                        mma_tf32(acc[m][ntl], a[m][4], a[m][5], a[m][6], a[m][7],
                                 Bv[i].z, Bv[i].w);
                }
            }
        }

        // -------- epilogue: paired-n-tile STG.128 (scale pre-folded) --------
#pragma unroll
        for (int m = 0; m < 4; m++) {
#pragma unroll
            for (int p = 0; p < 4; p++) {
                float* a0 = acc[m][2 * p];
                float* a1 = acc[m][2 * p + 1];
                int col = (ntb + 2 * p + odd) * 8 + (tig >> 1) * 4;
#pragma unroll
                for (int h = 0; h < 2; h++) {
                    int row = h ? rhi[m] : rlo[m];
                    float sx = odd ? a0[2 * h]     : a1[2 * h];
                    float sy = odd ? a0[2 * h + 1] : a1[2 * h + 1];
                    float rx = __shfl_xor_sync(0xffffffffu, sx, 1);
                    float ry = __shfl_xor_sync(0xffffffffu, sy, 1);
                    float4 v;
                    if (odd) { v.x = rx; v.y = ry; v.z = a1[2 * h]; v.w = a1[2 * h + 1]; }
                    else     { v.x = a0[2 * h]; v.y = a0[2 * h + 1]; v.z = rx; v.w = ry; }
                    if (row >= 0) *(float4*)(out + row + col) = v;
                }
                a0[0] = a0[1] = a0[2] = a0[3] = 0.f;
                a1[0] = a1[1] = a1[2] = a1[3] = 0.f;
            }
        }

        // -------- segment boundary: refill B (rare) --------
        if (havenext && nseg != cur_seg) {
            __syncthreads();   // all warps done reading old B
            const uint4* wp = g_wpack + nseg * 4096;
#pragma unroll
            for (int i = 0; i < 32; i++) Bs[tid + i * 128] = wp[tid + i * 128];
            cur_seg = nseg;
            // visibility certified by next tile's ks0 __syncthreads
        }
        seg = nseg;
#pragma unroll
        for (int j = 0; j < 4; j++) { cs[j] = ns[j]; cz[j] = nz[j]; }
    }
}

// ---------------- launch ----------------

extern "C" void kernel_launch(void* const* d_in, const int* in_sizes, int n_in,
                              void* d_out, int out_size) {
    const float* x = (const float*)d_in[0];   // [N, 16, 128]
    const float* y = (const float*)d_in[1];   // [N, 10]
    const float* w = (const float*)d_in[2];   // [10, 4, 128, 128]
    float* out = (float*)d_out;               // [N, 16, 128]

    cudaFuncSetAttribute(k_gemm, cudaFuncAttributeMaxDynamicSharedMemorySize,
                         SMEM_BYTES);

    k_prep<<<HBLK + WBLK, 256>>>(y, w);
    k_scan<<<1, 320>>>();
    k_scatter<<<HBLK, 256>>>();
    k_gemm<<<GRID_PERS, THREADS, SMEM_BYTES>>>(x, out);
}